// round 15
// baseline (speedup 1.0000x reference)
#include <cuda_runtime.h>

#define NB    1024      // batch
#define NS    32        // neighbors per hop
#define DIM   64
#define NREL  237
#define NRELP 238
#define NENTP 14542     // NENT + 1
#define WCS   256       // padded row stride for folded output weights

// ---------------- scratch (device globals; no allocation allowed) ----------
__device__ __align__(16) float g_R[NRELP * DIM];       // relf @ W_agg0 (row 237 = 0)
__device__ __align__(16) float g_S[NENTP * DIM];       // unmasked hop-2 sums per entity
__device__ __align__(16) float g_Wc[2 * DIM * WCS];    // W_agg1 @ W_out halves, padded rows
__device__ __align__(16) float g_W4p[DIM * WCS];       // mW4 padded to 1KB rows
__device__ __align__(16) float g_bc[NREL];             // b_agg1 @ (Wtop+Wbot) + b_out
__device__ __align__(16) float g_A[DIM * DIM];         // W_agg1 @ mW1[0:237]
__device__ __align__(16) float g_d[DIM];               // b_agg1 @ mW1[0:237] + mb1
__device__ __align__(16) float g_E[NB * DIM];          // 0.1 * eps @ mW1[0:237]
__device__ __align__(16) float g_pre[2 * NB * DIM];    // masked-mean hidden per side

__device__ __forceinline__ float selu_f(float x) {
    const float sc  = 1.0507009873554805f;
    const float asc = 1.7580993408473766f;   // sc * alpha
    return x > 0.f ? sc * x : asc * expm1f(x);
}

// fold-work block map inside k_Sw (these blocks come FIRST):
// 128 Wc | 64 A | 64 W4p | 1 bias | 256 E  => 513, then 1818 S blocks
#define FW_WC    0
#define FW_A     128
#define FW_W4    (128 + 64)            // 192
#define FW_BIAS  (FW_W4 + 64)          // 256
#define FW_E     (FW_BIAS + 1)         // 257
#define FW_TOTAL (FW_E + NB / 4)       // 513
#define S_BLOCKS ((NENTP + 7) / 8)     // 1818

// ---------------- kernel 0: R = relf @ W_agg0 ------------------------------
__global__ __launch_bounds__(256) void k_foldR(
    const float* __restrict__ relf, const float* __restrict__ W0)
{
    int bid = blockIdx.x, tid = threadIdx.x;
    if (tid < DIM) {
        float a0 = 0.f, a1 = 0.f, a2 = 0.f, a3 = 0.f;
        if (bid < NREL) {
            #pragma unroll
            for (int k = 0; k < DIM; k += 4) {
                a0 += relf[bid * DIM + k]     * W0[(k)     * DIM + tid];
                a1 += relf[bid * DIM + k + 1] * W0[(k + 1) * DIM + tid];
                a2 += relf[bid * DIM + k + 2] * W0[(k + 2) * DIM + tid];
                a3 += relf[bid * DIM + k + 3] * W0[(k + 3) * DIM + tid];
            }
        }
        g_R[bid * DIM + tid] = (a0 + a1) + (a2 + a3);
    }
}

// ---------------- kernel 1: merged fold-work + hop-2 entity sums -----------
__global__ __launch_bounds__(256) void k_Sw(
    const int* __restrict__ entity2edges, const int* __restrict__ edge2relation,
    const float* __restrict__ W1,   const float* __restrict__ b1,
    const float* __restrict__ Wout, const float* __restrict__ bout,
    const float* __restrict__ mW1,  const float* __restrict__ mb1,
    const float* __restrict__ mW4,  const float* __restrict__ eps)
{
    __shared__ float s_eps[4][240];
    __shared__ float s_part[4][256];

    int bid = blockIdx.x, tid = threadIdx.x;

    if (bid >= FW_TOTAL) {                   // ---- S gather path ----
        int w = tid >> 5, lane = tid & 31;
        int ent = (bid - FW_TOTAL) * 8 + w;
        if (ent >= NENTP) return;
        int e = entity2edges[ent * NS + lane];        // coalesced
        int r = edge2relation[e];                     // scattered gather
        const float2* R2 = (const float2*)g_R;
        float a0 = 0.f, a1 = 0.f, b0 = 0.f, b1_ = 0.f;
        float c0 = 0.f, c1 = 0.f, d0 = 0.f, d1 = 0.f;
        #pragma unroll
        for (int j = 0; j < 32; j += 4) {             // four independent chains
            int rj0 = __shfl_sync(0xffffffffu, r, j);
            int rj1 = __shfl_sync(0xffffffffu, r, j + 1);
            int rj2 = __shfl_sync(0xffffffffu, r, j + 2);
            int rj3 = __shfl_sync(0xffffffffu, r, j + 3);
            float2 f0 = R2[rj0 * 32 + lane];
            float2 f1 = R2[rj1 * 32 + lane];
            float2 f2 = R2[rj2 * 32 + lane];
            float2 f3 = R2[rj3 * 32 + lane];
            a0 += f0.x; a1 += f0.y;
            b0 += f1.x; b1_ += f1.y;
            c0 += f2.x; c1 += f2.y;
            d0 += f3.x; d1 += f3.y;
        }
        ((float2*)g_S)[ent * 32 + lane] =
            make_float2((a0 + b0) + (c0 + d0), (a1 + b1_) + (c1 + d1));
        return;
    }

    // ---- fold-work path ----
    if (bid < FW_A) {                        // Wc[s][i][:] = W_agg1[i,:] @ W_out half
        int idx = bid - FW_WC;
        int s = idx >> 6, i = idx & 63;
        if (tid < NREL) {
            float a0 = 0.f, a1 = 0.f, a2 = 0.f, a3 = 0.f;
            const float* w1r = W1 + i * NREL;
            const float* wo  = Wout + s * NREL * NREL;
            int k = 0;
            for (; k + 3 < NREL; k += 4) {
                a0 += w1r[k]     * wo[(k)     * NREL + tid];
                a1 += w1r[k + 1] * wo[(k + 1) * NREL + tid];
                a2 += w1r[k + 2] * wo[(k + 2) * NREL + tid];
                a3 += w1r[k + 3] * wo[(k + 3) * NREL + tid];
            }
            for (; k < NREL; k++) a0 += w1r[k] * wo[k * NREL + tid];
            g_Wc[s * DIM * WCS + i * WCS + tid] = (a0 + a1) + (a2 + a3);
        }
    } else if (bid < FW_W4) {                // A[i][:] = W_agg1[i,:] @ mW1[0:237]
        int i = bid - FW_A;
        if (tid < DIM) {
            float a0 = 0.f, a1 = 0.f, a2 = 0.f, a3 = 0.f;
            const float* w1r = W1 + i * NREL;
            int k = 0;
            for (; k + 3 < NREL; k += 4) {
                a0 += w1r[k]     * mW1[(k)     * DIM + tid];
                a1 += w1r[k + 1] * mW1[(k + 1) * DIM + tid];
                a2 += w1r[k + 2] * mW1[(k + 2) * DIM + tid];
                a3 += w1r[k + 3] * mW1[(k + 3) * DIM + tid];
            }
            for (; k < NREL; k++) a0 += w1r[k] * mW1[k * DIM + tid];
            g_A[i * DIM + tid] = (a0 + a1) + (a2 + a3);
        }
    } else if (bid < FW_BIAS) {              // padded copy of mW4
        int kk = bid - FW_W4;
        if (tid < NREL) g_W4p[kk * WCS + tid] = mW4[kk * NREL + tid];
    } else if (bid < FW_E) {                 // bias vectors
        if (tid < NREL) {
            float acc = bout[tid];
            for (int k = 0; k < NREL; k++)
                acc += b1[k] * (Wout[k * NREL + tid] + Wout[(k + NREL) * NREL + tid]);
            g_bc[tid] = acc;
        }
        if (tid < DIM) {
            float acc = mb1[tid];
            for (int k = 0; k < NREL; k++)
                acc += b1[k] * mW1[k * DIM + tid];
            g_d[tid] = acc;
        }
    } else {                                 // E = 0.1 * eps @ mW1, 4 batches/block
        int b0 = (bid - FW_E) * 4;
        int q = tid >> 6, j = tid & 63;
        for (int idx = tid; idx < 4 * NREL; idx += 256) {
            int row = idx / NREL, col = idx - row * NREL;
            s_eps[row][col] = eps[(b0 + row) * NREL + col];
        }
        __syncthreads();
        float e0 = 0.f, e1 = 0.f, e2 = 0.f, e3 = 0.f;
        int kb = q * 60, ke = (q == 3) ? NREL : (kb + 60);
        #pragma unroll 6
        for (int kk = kb; kk < ke; kk++) {
            float w = mW1[kk * DIM + j];
            e0 += s_eps[0][kk] * w;
            e1 += s_eps[1][kk] * w;
            e2 += s_eps[2][kk] * w;
            e3 += s_eps[3][kk] * w;
        }
        s_part[q][0 * 64 + j] = e0;
        s_part[q][1 * 64 + j] = e1;
        s_part[q][2 * 64 + j] = e2;
        s_part[q][3 * 64 + j] = e3;
        __syncthreads();
        {
            int i = tid >> 6, jj = tid & 63;
            float s = (s_part[0][tid] + s_part[1][tid])
                    + (s_part[2][tid] + s_part[3][tid]);
            g_E[(b0 + i) * DIM + jj] = 0.1f * s;
        }
    }
}

// ---------------- kernel 2: per-(b, side) aggregation, 4 warps/task --------
// Each warp handles 8 of 32 si steps; combine via smem. grid = 2*NB/4.
__global__ __launch_bounds__(512) void k_side(
    const int* __restrict__ entity_pairs, const int* __restrict__ train_edges,
    const int* __restrict__ entity2edges, const int* __restrict__ edge2entities,
    const int* __restrict__ edge2relation, const float* __restrict__ b_agg0)
{
    __shared__ float2 s_part[4][4][32];          // [tw][quarter][lane]

    int w = threadIdx.x >> 5, lane = threadIdx.x & 31;
    int tw = w >> 2, quarter = w & 3;
    int task = blockIdx.x * 4 + tw;              // [0, 2*NB)
    int b = task >> 1, side = task & 1;

    int te  = train_edges[b];
    int ent = entity_pairs[b * 2 + side];
    int e1   = entity2edges[ent * NS + lane];    // coalesced (dup across quarters, L1)
    float m1 = (e1 != te) ? 1.f : 0.f;
    int r1   = edge2relation[e1];                // scattered
    int ent2 = edge2entities[e1];                // scattered
    int r_te = edge2relation[te];

    const float2* R2 = (const float2*)g_R;
    const float2* S2 = (const float2*)g_S;
    float2 corr = R2[r_te * 32 + lane];
    float bias0 = b_agg0[2 * lane], bias1 = b_agg0[2 * lane + 1];
    float p0 = 0.f, p1 = 0.f, q0 = 0.f, q1 = 0.f;

    int s0 = quarter * 8;
    #pragma unroll
    for (int si = s0; si < s0 + 8; si += 2) {
        int entA = __shfl_sync(0xffffffffu, ent2, si);
        int entB = __shfl_sync(0xffffffffu, ent2, si + 1);
        int e2A  = entity2edges[entA * NS + lane];
        int e2B  = entity2edges[entB * NS + lane];
        float2 SA = S2[entA * 32 + lane];
        float2 SB = S2[entB * 32 + lane];
        unsigned balA = __ballot_sync(0xffffffffu, e2A == te);
        unsigned balB = __ballot_sync(0xffffffffu, e2B == te);
        float cntA = (float)__popc(balA);
        float cntB = (float)__popc(balB);
        int r1A = __shfl_sync(0xffffffffu, r1, si);
        int r1B = __shfl_sync(0xffffffffu, r1, si + 1);
        float2 eA = R2[r1A * 32 + lane];
        float2 eB = R2[r1B * 32 + lane];
        float mA = __shfl_sync(0xffffffffu, m1, si);
        float mB = __shfl_sync(0xffffffffu, m1, si + 1);
        p0 += mA * fmaxf((SA.x - cntA * corr.x) * (1.f / NS) + eA.x + bias0, 0.f);
        p1 += mA * fmaxf((SA.y - cntA * corr.y) * (1.f / NS) + eA.y + bias1, 0.f);
        q0 += mB * fmaxf((SB.x - cntB * corr.x) * (1.f / NS) + eB.x + bias0, 0.f);
        q1 += mB * fmaxf((SB.y - cntB * corr.y) * (1.f / NS) + eB.y + bias1, 0.f);
    }

    float2 res = make_float2(p0 + q0, p1 + q1);
    if (quarter != 0) s_part[tw][quarter][lane] = res;
    __syncthreads();
    if (quarter == 0) {
        float2 o1 = s_part[tw][1][lane];
        float2 o2 = s_part[tw][2][lane];
        float2 o3 = s_part[tw][3][lane];
        ((float2*)g_pre)[(side * NB + b) * 32 + lane] =
            make_float2(((res.x + o1.x) + (o2.x + o3.x)) * (1.f / NS),
                        ((res.y + o1.y) + (o2.y + o3.y)) * (1.f / NS));
    }
}

// ---------------- kernel 3: fused MLP(1-3) + output GEMM + layer4 + mul ----
// grid 512 = (128-batch-group pairs) x (2 j-halves); 512 threads.
// MLP (all 64 dims, duplicated per j-half): q = tid>>6, j = tid&63.
// Score: p = tid>>7 selects (side,k-half) for Wc and k-quarter for W4;
//        r = tid&127 is the column within this block's j-half.
__global__ __launch_bounds__(512) void k_tail(
    const float* __restrict__ t_in,
    const float* __restrict__ mW1,
    const float* __restrict__ mW2, const float* __restrict__ mb2,
    const float* __restrict__ mW3, const float* __restrict__ mb3,
    const float* __restrict__ mb4, float* __restrict__ out)
{
    __shared__ __align__(16) float s_q0[DIM * 4];    // [kk*4 + i]
    __shared__ __align__(16) float s_q1[DIM * 4];
    __shared__ __align__(16) float s_pm[DIM * 4];
    __shared__ __align__(16) float s_ha[DIM * 4];
    __shared__ __align__(16) float s_h3[DIM * 4];
    __shared__ float s_part[8][256];                 // [q][i*64 + j]
    __shared__ float s_t[4];
    __shared__ __align__(16) float4 s_po[4][128];
    __shared__ __align__(16) float4 s_pv[4][128];

    int tid = threadIdx.x;
    int q = tid >> 6, j = tid & 63;
    int bg = blockIdx.x >> 1, jh = blockIdx.x & 1;
    int b0 = bg * 4;

    if (tid < 256) {
        int i = tid >> 6, jj = tid & 63;
        float ti = t_in[b0 + i];
        if (jj == 0) s_t[i] = ti;
        float q0v = g_pre[(b0 + i) * DIM + jj];
        float q1v = g_pre[(NB + b0 + i) * DIM + jj];
        s_q0[jj * 4 + i] = q0v;
        s_q1[jj * 4 + i] = q1v;
        s_pm[jj * 4 + i] = (1.f - ti) * q0v + ti * q1v;
    }
    __syncthreads();

    // ---- layer 1 partials: pm@A (8 kk per slice), 4 batches per load ----
    {
        float a0 = 0.f, a1 = 0.f, a2 = 0.f, a3 = 0.f;
        int kA = q * 8;
        #pragma unroll
        for (int kk = kA; kk < kA + 8; kk++) {
            float w = g_A[kk * DIM + j];
            a0 += s_pm[kk * 4 + 0] * w;
            a1 += s_pm[kk * 4 + 1] * w;
            a2 += s_pm[kk * 4 + 2] * w;
            a3 += s_pm[kk * 4 + 3] * w;
        }
        s_part[q][0 * 64 + j] = a0;
        s_part[q][1 * 64 + j] = a1;
        s_part[q][2 * 64 + j] = a2;
        s_part[q][3 * 64 + j] = a3;
    }
    __syncthreads();
    if (tid < 256) {
        int i = tid >> 6, jj = tid & 63;
        float s = ((s_part[0][tid] + s_part[1][tid]) + (s_part[2][tid] + s_part[3][tid]))
                + ((s_part[4][tid] + s_part[5][tid]) + (s_part[6][tid] + s_part[7][tid]));
        s += g_E[(b0 + i) * DIM + jj] + g_d[jj] + s_t[i] * mW1[NREL * DIM + jj];
        s_ha[jj * 4 + i] = selu_f(s);
    }
    __syncthreads();

    // ---- layer 2 partials (8 kk each) ----
    {
        float n0 = 0.f, n1 = 0.f, n2 = 0.f, n3 = 0.f;
        int kA = q * 8;
        #pragma unroll
        for (int kk = kA; kk < kA + 8; kk++) {
            float w = mW2[kk * DIM + j];
            n0 += s_ha[kk * 4 + 0] * w;
            n1 += s_ha[kk * 4 + 1] * w;
            n2 += s_ha[kk * 4 + 2] * w;
            n3 += s_ha[kk * 4 + 3] * w;
        }
        s_part[q][0 * 64 + j] = n0;
        s_part[q][1 * 64 + j] = n1;
        s_part[q][2 * 64 + j] = n2;
        s_part[q][3 * 64 + j] = n3;
    }
    __syncthreads();
    if (tid < 256) {
        int i = tid >> 6, jj = tid & 63;
        float s = ((s_part[0][tid] + s_part[1][tid]) + (s_part[2][tid] + s_part[3][tid]))
                + ((s_part[4][tid] + s_part[5][tid]) + (s_part[6][tid] + s_part[7][tid]));
        s_pm[jj * 4 + i] = selu_f(s + mb2[jj]);
    }
    __syncthreads();

    // ---- layer 3 partials ----
    {
        float n0 = 0.f, n1 = 0.f, n2 = 0.f, n3 = 0.f;
        int kA = q * 8;
        #pragma unroll
        for (int kk = kA; kk < kA + 8; kk++) {
            float w = mW3[kk * DIM + j];
            n0 += s_pm[kk * 4 + 0] * w;
            n1 += s_pm[kk * 4 + 1] * w;
            n2 += s_pm[kk * 4 + 2] * w;
            n3 += s_pm[kk * 4 + 3] * w;
        }
        s_part[q][0 * 64 + j] = n0;
        s_part[q][1 * 64 + j] = n1;
        s_part[q][2 * 64 + j] = n2;
        s_part[q][3 * 64 + j] = n3;
    }
    __syncthreads();
    if (tid < 256) {
        int i = tid >> 6, jj = tid & 63;
        float s = ((s_part[0][tid] + s_part[1][tid]) + (s_part[2][tid] + s_part[3][tid]))
                + ((s_part[4][tid] + s_part[5][tid]) + (s_part[6][tid] + s_part[7][tid]));
        s_h3[jj * 4 + i] = selu_f(s + mb3[jj]);
    }
    __syncthreads();

    // ---- score: this block's 128-column half of Wc / W4 ----
    {
        int p = tid >> 7, r = tid & 127;
        int jo = jh * 128 + r;
        if (jo < NREL) {
            // ao partial: p>>1 selects side (Wc0/Wc1), p&1 selects k-half
            float4 ao = make_float4(0.f, 0.f, 0.f, 0.f);
            const float*  W  = g_Wc + (p >> 1) * DIM * WCS + jo;
            const float4* q4 = (const float4*)((p >> 1) ? s_q1 : s_q0);
            int k0 = (p & 1) * 32;
            #pragma unroll 8
            for (int kk = k0; kk < k0 + 32; kk++) {
                float w = W[kk * WCS];
                float4 qv = q4[kk];
                ao.x += qv.x * w; ao.y += qv.y * w;
                ao.z += qv.z * w; ao.w += qv.w * w;
            }
            s_po[p][r] = ao;

            // av partial: p selects k-quarter of W4
            float4 av = make_float4(0.f, 0.f, 0.f, 0.f);
            const float*  W4 = g_W4p + jo;
            const float4* h4 = (const float4*)s_h3;
            int k4 = p * 16;
            #pragma unroll 8
            for (int kk = k4; kk < k4 + 16; kk++) {
                float w = W4[kk * WCS];
                float4 hh = h4[kk];
                av.x += hh.x * w; av.y += hh.y * w;
                av.z += hh.z * w; av.w += hh.w * w;
            }
            s_pv[p][r] = av;
        }
        __syncthreads();

        if ((tid >> 7) == 0) {
            int r = tid & 127;
            int jo = jh * 128 + r;
            if (jo < NREL) {
                float bc = g_bc[jo], m4 = mb4[jo];
                float4 o0 = s_po[0][r], o1 = s_po[1][r];
                float4 o2 = s_po[2][r], o3 = s_po[3][r];
                float4 v0 = s_pv[0][r], v1 = s_pv[1][r];
                float4 v2 = s_pv[2][r], v3 = s_pv[3][r];
                out[(b0 + 0) * NREL + jo] =
                    (bc + (o0.x + o1.x) + (o2.x + o3.x)) *
                    (m4 + (v0.x + v1.x) + (v2.x + v3.x));
                out[(b0 + 1) * NREL + jo] =
                    (bc + (o0.y + o1.y) + (o2.y + o3.y)) *
                    (m4 + (v0.y + v1.y) + (v2.y + v3.y));
                out[(b0 + 2) * NREL + jo] =
                    (bc + (o0.z + o1.z) + (o2.z + o3.z)) *
                    (m4 + (v0.z + v1.z) + (v2.z + v3.z));
                out[(b0 + 3) * NREL + jo] =
                    (bc + (o0.w + o1.w) + (o2.w + o3.w)) *
                    (m4 + (v0.w + v1.w) + (v2.w + v3.w));
            }
        }
    }
}

// ---------------- launcher --------------------------------------------------
extern "C" void kernel_launch(void* const* d_in, const int* in_sizes, int n_in,
                              void* d_out, int out_size)
{
    const int*   entity_pairs  = (const int*)d_in[0];
    const int*   train_edges   = (const int*)d_in[1];
    // d_in[2] = labels : dead
    const int*   entity2edges  = (const int*)d_in[3];
    const int*   edge2entities = (const int*)d_in[4];
    const int*   edge2relation = (const int*)d_in[5];
    const float* t             = (const float*)d_in[6];
    const float* eps           = (const float*)d_in[7];
    const float* rel_feat      = (const float*)d_in[8];
    const float* W_agg0        = (const float*)d_in[9];
    const float* b_agg0        = (const float*)d_in[10];
    const float* W_agg1        = (const float*)d_in[11];
    const float* b_agg1        = (const float*)d_in[12];
    const float* W_out         = (const float*)d_in[13];
    const float* b_out         = (const float*)d_in[14];
    const float* mW1           = (const float*)d_in[15];
    const float* mb1           = (const float*)d_in[16];
    const float* mW2           = (const float*)d_in[17];
    const float* mb2           = (const float*)d_in[18];
    const float* mW3           = (const float*)d_in[19];
    const float* mb3           = (const float*)d_in[20];
    const float* mW4           = (const float*)d_in[21];
    const float* mb4           = (const float*)d_in[22];
    float* out = (float*)d_out;

    k_foldR<<<NRELP, 256>>>(rel_feat, W_agg0);
    k_Sw<<<FW_TOTAL + S_BLOCKS, 256>>>(entity2edges, edge2relation,
                                       W_agg1, b_agg1, W_out, b_out,
                                       mW1, mb1, mW4, eps);
    k_side<<<(2 * NB) / 4, 512>>>(entity_pairs, train_edges, entity2edges,
                                  edge2entities, edge2relation, b_agg0);
    k_tail<<<NB / 2, 512>>>(t, mW1, mW2, mb2, mW3, mb3, mb4, out);
}

// round 16
// speedup vs baseline: 1.0338x; 1.0338x over previous
#include <cuda_runtime.h>

#define NB    1024      // batch
#define NS    32        // neighbors per hop
#define DIM   64
#define NREL  237
#define NRELP 238
#define NENTP 14542     // NENT + 1
#define WCS   256       // padded row stride for folded output weights

// ---------------- scratch (device globals; no allocation allowed) ----------
__device__ __align__(16) float g_R[NRELP * DIM];       // relf @ W_agg0 (row 237 = 0)
__device__ __align__(16) float g_S[NENTP * DIM];       // unmasked hop-2 sums per entity
__device__ __align__(16) float g_Wc[2 * DIM * WCS];    // W_agg1 @ W_out halves, padded rows
__device__ __align__(16) float g_W4p[DIM * WCS];       // mW4 padded to 1KB rows
__device__ __align__(16) float g_bc[NREL];             // b_agg1 @ (Wtop+Wbot) + b_out
__device__ __align__(16) float g_A[DIM * DIM];         // W_agg1 @ mW1[0:237]
__device__ __align__(16) float g_d[DIM];               // b_agg1 @ mW1[0:237] + mb1
__device__ __align__(16) float g_E[NB * DIM];          // 0.1 * eps @ mW1[0:237]
__device__ __align__(16) float g_pre[2 * NB * DIM];    // masked-mean hidden per side

__device__ __forceinline__ float selu_f(float x) {
    const float sc  = 1.0507009873554805f;
    const float asc = 1.7580993408473766f;   // sc * alpha
    return x > 0.f ? sc * x : asc * expm1f(x);
}

// fold-work block map inside k_Sw (these blocks come FIRST):
// 128 Wc | 64 A | 64 W4p | 1 bias | 256 E  => 513, then 1818 S blocks
#define FW_WC    0
#define FW_A     128
#define FW_W4    (128 + 64)            // 192
#define FW_BIAS  (FW_W4 + 64)          // 256
#define FW_E     (FW_BIAS + 1)         // 257
#define FW_TOTAL (FW_E + NB / 4)       // 513
#define S_BLOCKS ((NENTP + 7) / 8)     // 1818

// ---------------- kernel 0: R = relf @ W_agg0 ------------------------------
__global__ __launch_bounds__(256) void k_foldR(
    const float* __restrict__ relf, const float* __restrict__ W0)
{
    int bid = blockIdx.x, tid = threadIdx.x;
    if (tid < DIM) {
        float a0 = 0.f, a1 = 0.f, a2 = 0.f, a3 = 0.f;
        if (bid < NREL) {
            #pragma unroll
            for (int k = 0; k < DIM; k += 4) {
                a0 += relf[bid * DIM + k]     * W0[(k)     * DIM + tid];
                a1 += relf[bid * DIM + k + 1] * W0[(k + 1) * DIM + tid];
                a2 += relf[bid * DIM + k + 2] * W0[(k + 2) * DIM + tid];
                a3 += relf[bid * DIM + k + 3] * W0[(k + 3) * DIM + tid];
            }
        }
        g_R[bid * DIM + tid] = (a0 + a1) + (a2 + a3);
    }
}

// ---------------- kernel 1: merged fold-work + hop-2 entity sums -----------
__global__ __launch_bounds__(256) void k_Sw(
    const int* __restrict__ entity2edges, const int* __restrict__ edge2relation,
    const float* __restrict__ W1,   const float* __restrict__ b1,
    const float* __restrict__ Wout, const float* __restrict__ bout,
    const float* __restrict__ mW1,  const float* __restrict__ mb1,
    const float* __restrict__ mW4,  const float* __restrict__ eps)
{
    __shared__ float s_eps[4][240];
    __shared__ float s_part[4][256];

    int bid = blockIdx.x, tid = threadIdx.x;

    if (bid >= FW_TOTAL) {                   // ---- S gather path ----
        int w = tid >> 5, lane = tid & 31;
        int ent = (bid - FW_TOTAL) * 8 + w;
        if (ent >= NENTP) return;
        int e = entity2edges[ent * NS + lane];        // coalesced
        int r = edge2relation[e];                     // scattered gather
        const float2* R2 = (const float2*)g_R;
        float a0 = 0.f, a1 = 0.f, b0 = 0.f, b1_ = 0.f;
        float c0 = 0.f, c1 = 0.f, d0 = 0.f, d1 = 0.f;
        #pragma unroll
        for (int j = 0; j < 32; j += 4) {             // four independent chains
            int rj0 = __shfl_sync(0xffffffffu, r, j);
            int rj1 = __shfl_sync(0xffffffffu, r, j + 1);
            int rj2 = __shfl_sync(0xffffffffu, r, j + 2);
            int rj3 = __shfl_sync(0xffffffffu, r, j + 3);
            float2 f0 = R2[rj0 * 32 + lane];
            float2 f1 = R2[rj1 * 32 + lane];
            float2 f2 = R2[rj2 * 32 + lane];
            float2 f3 = R2[rj3 * 32 + lane];
            a0 += f0.x; a1 += f0.y;
            b0 += f1.x; b1_ += f1.y;
            c0 += f2.x; c1 += f2.y;
            d0 += f3.x; d1 += f3.y;
        }
        ((float2*)g_S)[ent * 32 + lane] =
            make_float2((a0 + b0) + (c0 + d0), (a1 + b1_) + (c1 + d1));
        return;
    }

    // ---- fold-work path ----
    if (bid < FW_A) {                        // Wc[s][i][:] = W_agg1[i,:] @ W_out half
        int idx = bid - FW_WC;
        int s = idx >> 6, i = idx & 63;
        if (tid < NREL) {
            float a0 = 0.f, a1 = 0.f, a2 = 0.f, a3 = 0.f;
            const float* w1r = W1 + i * NREL;
            const float* wo  = Wout + s * NREL * NREL;
            int k = 0;
            for (; k + 3 < NREL; k += 4) {
                a0 += w1r[k]     * wo[(k)     * NREL + tid];
                a1 += w1r[k + 1] * wo[(k + 1) * NREL + tid];
                a2 += w1r[k + 2] * wo[(k + 2) * NREL + tid];
                a3 += w1r[k + 3] * wo[(k + 3) * NREL + tid];
            }
            for (; k < NREL; k++) a0 += w1r[k] * wo[k * NREL + tid];
            g_Wc[s * DIM * WCS + i * WCS + tid] = (a0 + a1) + (a2 + a3);
        }
    } else if (bid < FW_W4) {                // A[i][:] = W_agg1[i,:] @ mW1[0:237]
        int i = bid - FW_A;
        if (tid < DIM) {
            float a0 = 0.f, a1 = 0.f, a2 = 0.f, a3 = 0.f;
            const float* w1r = W1 + i * NREL;
            int k = 0;
            for (; k + 3 < NREL; k += 4) {
                a0 += w1r[k]     * mW1[(k)     * DIM + tid];
                a1 += w1r[k + 1] * mW1[(k + 1) * DIM + tid];
                a2 += w1r[k + 2] * mW1[(k + 2) * DIM + tid];
                a3 += w1r[k + 3] * mW1[(k + 3) * DIM + tid];
            }
            for (; k < NREL; k++) a0 += w1r[k] * mW1[k * DIM + tid];
            g_A[i * DIM + tid] = (a0 + a1) + (a2 + a3);
        }
    } else if (bid < FW_BIAS) {              // padded copy of mW4
        int kk = bid - FW_W4;
        if (tid < NREL) g_W4p[kk * WCS + tid] = mW4[kk * NREL + tid];
    } else if (bid < FW_E) {                 // bias vectors
        if (tid < NREL) {
            float acc = bout[tid];
            for (int k = 0; k < NREL; k++)
                acc += b1[k] * (Wout[k * NREL + tid] + Wout[(k + NREL) * NREL + tid]);
            g_bc[tid] = acc;
        }
        if (tid < DIM) {
            float acc = mb1[tid];
            for (int k = 0; k < NREL; k++)
                acc += b1[k] * mW1[k * DIM + tid];
            g_d[tid] = acc;
        }
    } else {                                 // E = 0.1 * eps @ mW1, 4 batches/block
        int b0 = (bid - FW_E) * 4;
        int q = tid >> 6, j = tid & 63;
        for (int idx = tid; idx < 4 * NREL; idx += 256) {
            int row = idx / NREL, col = idx - row * NREL;
            s_eps[row][col] = eps[(b0 + row) * NREL + col];
        }
        __syncthreads();
        float e0 = 0.f, e1 = 0.f, e2 = 0.f, e3 = 0.f;
        int kb = q * 60, ke = (q == 3) ? NREL : (kb + 60);
        #pragma unroll 6
        for (int kk = kb; kk < ke; kk++) {
            float w = mW1[kk * DIM + j];
            e0 += s_eps[0][kk] * w;
            e1 += s_eps[1][kk] * w;
            e2 += s_eps[2][kk] * w;
            e3 += s_eps[3][kk] * w;
        }
        s_part[q][0 * 64 + j] = e0;
        s_part[q][1 * 64 + j] = e1;
        s_part[q][2 * 64 + j] = e2;
        s_part[q][3 * 64 + j] = e3;
        __syncthreads();
        {
            int i = tid >> 6, jj = tid & 63;
            float s = (s_part[0][tid] + s_part[1][tid])
                    + (s_part[2][tid] + s_part[3][tid]);
            g_E[(b0 + i) * DIM + jj] = 0.1f * s;
        }
    }
}

// ---------------- kernel 2: per-(b, side) aggregation via S correction -----
// 2 warps per task: each handles 16 of 32 si steps; combine via smem.
__global__ __launch_bounds__(512) void k_side(
    const int* __restrict__ entity_pairs, const int* __restrict__ train_edges,
    const int* __restrict__ entity2edges, const int* __restrict__ edge2entities,
    const int* __restrict__ edge2relation, const float* __restrict__ b_agg0)
{
    __shared__ float2 s_part[8][32];

    int w = threadIdx.x >> 5, lane = threadIdx.x & 31;
    int tw = w >> 1, half = w & 1;
    int task = blockIdx.x * 8 + tw;              // [0, 2*NB)
    int b = task >> 1, side = task & 1;

    int te  = train_edges[b];
    int ent = entity_pairs[b * 2 + side];
    int e1   = entity2edges[ent * NS + lane];    // coalesced (dup across halves, L1)
    float m1 = (e1 != te) ? 1.f : 0.f;
    int r1   = edge2relation[e1];                // scattered
    int ent2 = edge2entities[e1];                // scattered
    int r_te = edge2relation[te];

    const float2* R2 = (const float2*)g_R;
    const float2* S2 = (const float2*)g_S;
    float2 corr = R2[r_te * 32 + lane];
    float bias0 = b_agg0[2 * lane], bias1 = b_agg0[2 * lane + 1];
    float p0 = 0.f, p1 = 0.f, q0 = 0.f, q1 = 0.f;

    int s0 = half * 16;
    #pragma unroll 2
    for (int si = s0; si < s0 + 16; si += 2) {
        int entA = __shfl_sync(0xffffffffu, ent2, si);
        int entB = __shfl_sync(0xffffffffu, ent2, si + 1);
        int e2A  = entity2edges[entA * NS + lane];
        int e2B  = entity2edges[entB * NS + lane];
        float2 SA = S2[entA * 32 + lane];
        float2 SB = S2[entB * 32 + lane];
        unsigned balA = __ballot_sync(0xffffffffu, e2A == te);
        unsigned balB = __ballot_sync(0xffffffffu, e2B == te);
        float cntA = (float)__popc(balA);
        float cntB = (float)__popc(balB);
        int r1A = __shfl_sync(0xffffffffu, r1, si);
        int r1B = __shfl_sync(0xffffffffu, r1, si + 1);
        float2 eA = R2[r1A * 32 + lane];
        float2 eB = R2[r1B * 32 + lane];
        float mA = __shfl_sync(0xffffffffu, m1, si);
        float mB = __shfl_sync(0xffffffffu, m1, si + 1);
        p0 += mA * fmaxf((SA.x - cntA * corr.x) * (1.f / NS) + eA.x + bias0, 0.f);
        p1 += mA * fmaxf((SA.y - cntA * corr.y) * (1.f / NS) + eA.y + bias1, 0.f);
        q0 += mB * fmaxf((SB.x - cntB * corr.x) * (1.f / NS) + eB.x + bias0, 0.f);
        q1 += mB * fmaxf((SB.y - cntB * corr.y) * (1.f / NS) + eB.y + bias1, 0.f);
    }

    float2 res = make_float2(p0 + q0, p1 + q1);
    if (half == 1) s_part[tw][lane] = res;
    __syncthreads();
    if (half == 0) {
        float2 o = s_part[tw][lane];
        ((float2*)g_pre)[(side * NB + b) * 32 + lane] =
            make_float2((res.x + o.x) * (1.f / NS), (res.y + o.y) * (1.f / NS));
    }
}

// ---------------- kernel 3: fused MLP(1-3) + output GEMM + layer4 + mul ----
// grid 512 = (128-batch-group pairs) x (2 j-halves); 512 threads.
// MLP (all 64 dims, duplicated per j-half): q = tid>>6, j = tid&63.
// Score: p = tid>>7 selects (side,k-half) for Wc and k-quarter for W4;
//        r = tid&127 is the column within this block's j-half.
__global__ __launch_bounds__(512) void k_tail(
    const float* __restrict__ t_in,
    const float* __restrict__ mW1,
    const float* __restrict__ mW2, const float* __restrict__ mb2,
    const float* __restrict__ mW3, const float* __restrict__ mb3,
    const float* __restrict__ mb4, float* __restrict__ out)
{
    __shared__ __align__(16) float s_q0[DIM * 4];    // [kk*4 + i]
    __shared__ __align__(16) float s_q1[DIM * 4];
    __shared__ __align__(16) float s_pm[DIM * 4];
    __shared__ __align__(16) float s_ha[DIM * 4];
    __shared__ __align__(16) float s_h3[DIM * 4];
    __shared__ float s_part[8][256];                 // [q][i*64 + j]
    __shared__ float s_t[4];
    __shared__ __align__(16) float4 s_po[4][128];
    __shared__ __align__(16) float4 s_pv[4][128];

    int tid = threadIdx.x;
    int q = tid >> 6, j = tid & 63;
    int bg = blockIdx.x >> 1, jh = blockIdx.x & 1;
    int b0 = bg * 4;

    if (tid < 256) {
        int i = tid >> 6, jj = tid & 63;
        float ti = t_in[b0 + i];
        if (jj == 0) s_t[i] = ti;
        float q0v = g_pre[(b0 + i) * DIM + jj];
        float q1v = g_pre[(NB + b0 + i) * DIM + jj];
        s_q0[jj * 4 + i] = q0v;
        s_q1[jj * 4 + i] = q1v;
        s_pm[jj * 4 + i] = (1.f - ti) * q0v + ti * q1v;
    }
    __syncthreads();

    // ---- layer 1 partials: pm@A (8 kk per slice), 4 batches per load ----
    {
        float a0 = 0.f, a1 = 0.f, a2 = 0.f, a3 = 0.f;
        int kA = q * 8;
        #pragma unroll
        for (int kk = kA; kk < kA + 8; kk++) {
            float w = g_A[kk * DIM + j];
            a0 += s_pm[kk * 4 + 0] * w;
            a1 += s_pm[kk * 4 + 1] * w;
            a2 += s_pm[kk * 4 + 2] * w;
            a3 += s_pm[kk * 4 + 3] * w;
        }
        s_part[q][0 * 64 + j] = a0;
        s_part[q][1 * 64 + j] = a1;
        s_part[q][2 * 64 + j] = a2;
        s_part[q][3 * 64 + j] = a3;
    }
    __syncthreads();
    if (tid < 256) {
        int i = tid >> 6, jj = tid & 63;
        float s = ((s_part[0][tid] + s_part[1][tid]) + (s_part[2][tid] + s_part[3][tid]))
                + ((s_part[4][tid] + s_part[5][tid]) + (s_part[6][tid] + s_part[7][tid]));
        s += g_E[(b0 + i) * DIM + jj] + g_d[jj] + s_t[i] * mW1[NREL * DIM + jj];
        s_ha[jj * 4 + i] = selu_f(s);
    }
    __syncthreads();

    // ---- layer 2 partials (8 kk each) ----
    {
        float n0 = 0.f, n1 = 0.f, n2 = 0.f, n3 = 0.f;
        int kA = q * 8;
        #pragma unroll
        for (int kk = kA; kk < kA + 8; kk++) {
            float w = mW2[kk * DIM + j];
            n0 += s_ha[kk * 4 + 0] * w;
            n1 += s_ha[kk * 4 + 1] * w;
            n2 += s_ha[kk * 4 + 2] * w;
            n3 += s_ha[kk * 4 + 3] * w;
        }
        s_part[q][0 * 64 + j] = n0;
        s_part[q][1 * 64 + j] = n1;
        s_part[q][2 * 64 + j] = n2;
        s_part[q][3 * 64 + j] = n3;
    }
    __syncthreads();
    if (tid < 256) {
        int i = tid >> 6, jj = tid & 63;
        float s = ((s_part[0][tid] + s_part[1][tid]) + (s_part[2][tid] + s_part[3][tid]))
                + ((s_part[4][tid] + s_part[5][tid]) + (s_part[6][tid] + s_part[7][tid]));
        s_pm[jj * 4 + i] = selu_f(s + mb2[jj]);
    }
    __syncthreads();

    // ---- layer 3 partials ----
    {
        float n0 = 0.f, n1 = 0.f, n2 = 0.f, n3 = 0.f;
        int kA = q * 8;
        #pragma unroll
        for (int kk = kA; kk < kA + 8; kk++) {
            float w = mW3[kk * DIM + j];
            n0 += s_pm[kk * 4 + 0] * w;
            n1 += s_pm[kk * 4 + 1] * w;
            n2 += s_pm[kk * 4 + 2] * w;
            n3 += s_pm[kk * 4 + 3] * w;
        }
        s_part[q][0 * 64 + j] = n0;
        s_part[q][1 * 64 + j] = n1;
        s_part[q][2 * 64 + j] = n2;
        s_part[q][3 * 64 + j] = n3;
    }
    __syncthreads();
    if (tid < 256) {
        int i = tid >> 6, jj = tid & 63;
        float s = ((s_part[0][tid] + s_part[1][tid]) + (s_part[2][tid] + s_part[3][tid]))
                + ((s_part[4][tid] + s_part[5][tid]) + (s_part[6][tid] + s_part[7][tid]));
        s_h3[jj * 4 + i] = selu_f(s + mb3[jj]);
    }
    __syncthreads();

    // ---- score: this block's 128-column half of Wc / W4 ----
    {
        int p = tid >> 7, r = tid & 127;
        int jo = jh * 128 + r;
        if (jo < NREL) {
            // ao partial: p>>1 selects side (Wc0/Wc1), p&1 selects k-half
            float4 ao = make_float4(0.f, 0.f, 0.f, 0.f);
            const float*  W  = g_Wc + (p >> 1) * DIM * WCS + jo;
            const float4* q4 = (const float4*)((p >> 1) ? s_q1 : s_q0);
            int k0 = (p & 1) * 32;
            #pragma unroll 8
            for (int kk = k0; kk < k0 + 32; kk++) {
                float w = W[kk * WCS];
                float4 qv = q4[kk];
                ao.x += qv.x * w; ao.y += qv.y * w;
                ao.z += qv.z * w; ao.w += qv.w * w;
            }
            s_po[p][r] = ao;

            // av partial: p selects k-quarter of W4
            float4 av = make_float4(0.f, 0.f, 0.f, 0.f);
            const float*  W4 = g_W4p + jo;
            const float4* h4 = (const float4*)s_h3;
            int k4 = p * 16;
            #pragma unroll 8
            for (int kk = k4; kk < k4 + 16; kk++) {
                float w = W4[kk * WCS];
                float4 hh = h4[kk];
                av.x += hh.x * w; av.y += hh.y * w;
                av.z += hh.z * w; av.w += hh.w * w;
            }
            s_pv[p][r] = av;
        }
        __syncthreads();

        if ((tid >> 7) == 0) {
            int r = tid & 127;
            int jo = jh * 128 + r;
            if (jo < NREL) {
                float bc = g_bc[jo], m4 = mb4[jo];
                float4 o0 = s_po[0][r], o1 = s_po[1][r];
                float4 o2 = s_po[2][r], o3 = s_po[3][r];
                float4 v0 = s_pv[0][r], v1 = s_pv[1][r];
                float4 v2 = s_pv[2][r], v3 = s_pv[3][r];
                out[(b0 + 0) * NREL + jo] =
                    (bc + (o0.x + o1.x) + (o2.x + o3.x)) *
                    (m4 + (v0.x + v1.x) + (v2.x + v3.x));
                out[(b0 + 1) * NREL + jo] =
                    (bc + (o0.y + o1.y) + (o2.y + o3.y)) *
                    (m4 + (v0.y + v1.y) + (v2.y + v3.y));
                out[(b0 + 2) * NREL + jo] =
                    (bc + (o0.z + o1.z) + (o2.z + o3.z)) *
                    (m4 + (v0.z + v1.z) + (v2.z + v3.z));
                out[(b0 + 3) * NREL + jo] =
                    (bc + (o0.w + o1.w) + (o2.w + o3.w)) *
                    (m4 + (v0.w + v1.w) + (v2.w + v3.w));
            }
        }
    }
}

// ---------------- launcher --------------------------------------------------
extern "C" void kernel_launch(void* const* d_in, const int* in_sizes, int n_in,
                              void* d_out, int out_size)
{
    const int*   entity_pairs  = (const int*)d_in[0];
    const int*   train_edges   = (const int*)d_in[1];
    // d_in[2] = labels : dead
    const int*   entity2edges  = (const int*)d_in[3];
    const int*   edge2entities = (const int*)d_in[4];
    const int*   edge2relation = (const int*)d_in[5];
    const float* t             = (const float*)d_in[6];
    const float* eps           = (const float*)d_in[7];
    const float* rel_feat      = (const float*)d_in[8];
    const float* W_agg0        = (const float*)d_in[9];
    const float* b_agg0        = (const float*)d_in[10];
    const float* W_agg1        = (const float*)d_in[11];
    const float* b_agg1        = (const float*)d_in[12];
    const float* W_out         = (const float*)d_in[13];
    const float* b_out         = (const float*)d_in[14];
    const float* mW1           = (const float*)d_in[15];
    const float* mb1           = (const float*)d_in[16];
    const float* mW2           = (const float*)d_in[17];
    const float* mb2           = (const float*)d_in[18];
    const float* mW3           = (const float*)d_in[19];
    const float* mb3           = (const float*)d_in[20];
    const float* mW4           = (const float*)d_in[21];
    const float* mb4           = (const float*)d_in[22];
    float* out = (float*)d_out;

    k_foldR<<<NRELP, 256>>>(rel_feat, W_agg0);
    k_Sw<<<FW_TOTAL + S_BLOCKS, 256>>>(entity2edges, edge2relation,
                                       W_agg1, b_agg1, W_out, b_out,
                                       mW1, mb1, mW4, eps);
    k_side<<<(2 * NB) / 8, 512>>>(entity_pairs, train_edges, entity2edges,
                                  edge2entities, edge2relation, b_agg0);
    k_tail<<<NB / 2, 512>>>(t, mW1, mW2, mb2, mW3, mb3, mb4, out);
}

// round 17
// speedup vs baseline: 1.0942x; 1.0585x over previous
#include <cuda_runtime.h>

#define NB    1024      // batch
#define NS    32        // neighbors per hop
#define DIM   64
#define NREL  237
#define NRELP 238
#define NENTP 14542     // NENT + 1
#define WCS   256       // padded row stride for folded output weights

// ---------------- scratch (device globals; no allocation allowed) ----------
__device__ __align__(16) float g_R[NRELP * DIM];       // relf @ W_agg0 (row 237 = 0)
__device__ __align__(16) float g_S[NENTP * DIM];       // unmasked hop-2 sums per entity
__device__ __align__(16) float g_Wc[2 * DIM * WCS];    // W_agg1 @ W_out halves, padded rows
__device__ __align__(16) float g_W4p[DIM * WCS];       // mW4 padded to 1KB rows
__device__ __align__(16) float g_bc[NREL];             // b_agg1 @ (Wtop+Wbot) + b_out
__device__ __align__(16) float g_A[DIM * DIM];         // W_agg1 @ mW1[0:237]
__device__ __align__(16) float g_d[DIM];               // b_agg1 @ mW1[0:237] + mb1
__device__ __align__(16) float g_E[NB * DIM];          // 0.1 * eps @ mW1[0:237]

__device__ __forceinline__ float selu_f(float x) {
    const float sc  = 1.0507009873554805f;
    const float asc = 1.7580993408473766f;   // sc * alpha
    return x > 0.f ? sc * x : asc * expm1f(x);
}

// fold-work block map inside k_Sw (these blocks come FIRST):
// 128 Wc | 64 A | 64 W4p | 1 bias | 256 E  => 513, then 1818 S blocks
#define FW_WC    0
#define FW_A     128
#define FW_W4    (128 + 64)            // 192
#define FW_BIAS  (FW_W4 + 64)          // 256
#define FW_E     (FW_BIAS + 1)         // 257
#define FW_TOTAL (FW_E + NB / 4)       // 513
#define S_BLOCKS ((NENTP + 7) / 8)     // 1818

// ---------------- kernel 0: R = relf @ W_agg0 ------------------------------
__global__ __launch_bounds__(256) void k_foldR(
    const float* __restrict__ relf, const float* __restrict__ W0)
{
    int bid = blockIdx.x, tid = threadIdx.x;
    if (tid < DIM) {
        float a0 = 0.f, a1 = 0.f, a2 = 0.f, a3 = 0.f;
        if (bid < NREL) {
            #pragma unroll
            for (int k = 0; k < DIM; k += 4) {
                a0 += relf[bid * DIM + k]     * W0[(k)     * DIM + tid];
                a1 += relf[bid * DIM + k + 1] * W0[(k + 1) * DIM + tid];
                a2 += relf[bid * DIM + k + 2] * W0[(k + 2) * DIM + tid];
                a3 += relf[bid * DIM + k + 3] * W0[(k + 3) * DIM + tid];
            }
        }
        g_R[bid * DIM + tid] = (a0 + a1) + (a2 + a3);
    }
}

// ---------------- kernel 1: merged fold-work + hop-2 entity sums -----------
__global__ __launch_bounds__(256) void k_Sw(
    const int* __restrict__ entity2edges, const int* __restrict__ edge2relation,
    const float* __restrict__ W1,   const float* __restrict__ b1,
    const float* __restrict__ Wout, const float* __restrict__ bout,
    const float* __restrict__ mW1,  const float* __restrict__ mb1,
    const float* __restrict__ mW4,  const float* __restrict__ eps)
{
    __shared__ float s_eps[4][240];
    __shared__ float s_part[4][256];

    int bid = blockIdx.x, tid = threadIdx.x;

    if (bid >= FW_TOTAL) {                   // ---- S gather path ----
        int w = tid >> 5, lane = tid & 31;
        int ent = (bid - FW_TOTAL) * 8 + w;
        if (ent >= NENTP) return;
        int e = entity2edges[ent * NS + lane];        // coalesced
        int r = edge2relation[e];                     // scattered gather
        const float2* R2 = (const float2*)g_R;
        float a0 = 0.f, a1 = 0.f, b0 = 0.f, b1_ = 0.f;
        float c0 = 0.f, c1 = 0.f, d0 = 0.f, d1 = 0.f;
        #pragma unroll
        for (int j = 0; j < 32; j += 4) {             // four independent chains
            int rj0 = __shfl_sync(0xffffffffu, r, j);
            int rj1 = __shfl_sync(0xffffffffu, r, j + 1);
            int rj2 = __shfl_sync(0xffffffffu, r, j + 2);
            int rj3 = __shfl_sync(0xffffffffu, r, j + 3);
            float2 f0 = R2[rj0 * 32 + lane];
            float2 f1 = R2[rj1 * 32 + lane];
            float2 f2 = R2[rj2 * 32 + lane];
            float2 f3 = R2[rj3 * 32 + lane];
            a0 += f0.x; a1 += f0.y;
            b0 += f1.x; b1_ += f1.y;
            c0 += f2.x; c1 += f2.y;
            d0 += f3.x; d1 += f3.y;
        }
        ((float2*)g_S)[ent * 32 + lane] =
            make_float2((a0 + b0) + (c0 + d0), (a1 + b1_) + (c1 + d1));
        return;
    }

    // ---- fold-work path ----
    if (bid < FW_A) {                        // Wc[s][i][:] = W_agg1[i,:] @ W_out half
        int idx = bid - FW_WC;
        int s = idx >> 6, i = idx & 63;
        if (tid < NREL) {
            float a0 = 0.f, a1 = 0.f, a2 = 0.f, a3 = 0.f;
            const float* w1r = W1 + i * NREL;
            const float* wo  = Wout + s * NREL * NREL;
            int k = 0;
            for (; k + 3 < NREL; k += 4) {
                a0 += w1r[k]     * wo[(k)     * NREL + tid];
                a1 += w1r[k + 1] * wo[(k + 1) * NREL + tid];
                a2 += w1r[k + 2] * wo[(k + 2) * NREL + tid];
                a3 += w1r[k + 3] * wo[(k + 3) * NREL + tid];
            }
            for (; k < NREL; k++) a0 += w1r[k] * wo[k * NREL + tid];
            g_Wc[s * DIM * WCS + i * WCS + tid] = (a0 + a1) + (a2 + a3);
        }
    } else if (bid < FW_W4) {                // A[i][:] = W_agg1[i,:] @ mW1[0:237]
        int i = bid - FW_A;
        if (tid < DIM) {
            float a0 = 0.f, a1 = 0.f, a2 = 0.f, a3 = 0.f;
            const float* w1r = W1 + i * NREL;
            int k = 0;
            for (; k + 3 < NREL; k += 4) {
                a0 += w1r[k]     * mW1[(k)     * DIM + tid];
                a1 += w1r[k + 1] * mW1[(k + 1) * DIM + tid];
                a2 += w1r[k + 2] * mW1[(k + 2) * DIM + tid];
                a3 += w1r[k + 3] * mW1[(k + 3) * DIM + tid];
            }
            for (; k < NREL; k++) a0 += w1r[k] * mW1[k * DIM + tid];
            g_A[i * DIM + tid] = (a0 + a1) + (a2 + a3);
        }
    } else if (bid < FW_BIAS) {              // padded copy of mW4
        int kk = bid - FW_W4;
        if (tid < NREL) g_W4p[kk * WCS + tid] = mW4[kk * NREL + tid];
    } else if (bid < FW_E) {                 // bias vectors
        if (tid < NREL) {
            float acc = bout[tid];
            for (int k = 0; k < NREL; k++)
                acc += b1[k] * (Wout[k * NREL + tid] + Wout[(k + NREL) * NREL + tid]);
            g_bc[tid] = acc;
        }
        if (tid < DIM) {
            float acc = mb1[tid];
            for (int k = 0; k < NREL; k++)
                acc += b1[k] * mW1[k * DIM + tid];
            g_d[tid] = acc;
        }
    } else {                                 // E = 0.1 * eps @ mW1, 4 batches/block
        int b0 = (bid - FW_E) * 4;
        int q = tid >> 6, j = tid & 63;
        for (int idx = tid; idx < 4 * NREL; idx += 256) {
            int row = idx / NREL, col = idx - row * NREL;
            s_eps[row][col] = eps[(b0 + row) * NREL + col];
        }
        __syncthreads();
        float e0 = 0.f, e1 = 0.f, e2 = 0.f, e3 = 0.f;
        int kb = q * 60, ke = (q == 3) ? NREL : (kb + 60);
        #pragma unroll 6
        for (int kk = kb; kk < ke; kk++) {
            float w = mW1[kk * DIM + j];
            e0 += s_eps[0][kk] * w;
            e1 += s_eps[1][kk] * w;
            e2 += s_eps[2][kk] * w;
            e3 += s_eps[3][kk] * w;
        }
        s_part[q][0 * 64 + j] = e0;
        s_part[q][1 * 64 + j] = e1;
        s_part[q][2 * 64 + j] = e2;
        s_part[q][3 * 64 + j] = e3;
        __syncthreads();
        {
            int i = tid >> 6, jj = tid & 63;
            float s = (s_part[0][tid] + s_part[1][tid])
                    + (s_part[2][tid] + s_part[3][tid]);
            g_E[(b0 + i) * DIM + jj] = 0.1f * s;
        }
    }
}

// ---------------- kernel 2: FUSED side-gather + MLP + output + scores ------
// grid NB/4 = 256 blocks x 512 threads; block handles batches b0..b0+3.
// Side section: 8 tasks (4 batches x 2 sides) x 2 warps each, pre -> smem.
// Then MLP layers 1-3, folded output GEMM, layer 4, multiply (R14-proven).
__global__ __launch_bounds__(512) void k_fused(
    const int* __restrict__ entity_pairs, const int* __restrict__ train_edges,
    const int* __restrict__ entity2edges, const int* __restrict__ edge2entities,
    const int* __restrict__ edge2relation, const float* __restrict__ b_agg0,
    const float* __restrict__ t_in,
    const float* __restrict__ mW1,
    const float* __restrict__ mW2, const float* __restrict__ mb2,
    const float* __restrict__ mW3, const float* __restrict__ mb3,
    const float* __restrict__ mb4, float* __restrict__ out)
{
    __shared__ float2 s_sp[8][32];                   // side half-1 partials
    __shared__ float  s_pre[8][DIM];                 // [task = i*2+side][dim]
    __shared__ __align__(16) float s_q0[DIM * 4];    // [kk*4 + i]
    __shared__ __align__(16) float s_q1[DIM * 4];
    __shared__ __align__(16) float s_pm[DIM * 4];
    __shared__ __align__(16) float s_ha[DIM * 4];
    __shared__ __align__(16) float s_h3[DIM * 4];
    __shared__ float s_part[8][256];                 // [q][i*64 + j]
    __shared__ float s_t[4];
    __shared__ __align__(16) float4 s_po[512];
    __shared__ __align__(16) float4 s_pv[512];

    int tid = threadIdx.x;
    int b0 = blockIdx.x * 4;

    // ================= side gather section (16 warps, 8 tasks) =============
    {
        int w = tid >> 5, lane = tid & 31;
        int tw = w >> 1, half = w & 1;
        int b = b0 + (tw >> 1), side = tw & 1;

        int te  = train_edges[b];
        int ent = entity_pairs[b * 2 + side];
        int e1   = entity2edges[ent * NS + lane];    // coalesced (dup per half, L1)
        float m1 = (e1 != te) ? 1.f : 0.f;
        int r1   = edge2relation[e1];                // scattered
        int ent2 = edge2entities[e1];                // scattered
        int r_te = edge2relation[te];

        const float2* R2 = (const float2*)g_R;
        const float2* S2 = (const float2*)g_S;
        float2 corr = R2[r_te * 32 + lane];
        float bias0 = b_agg0[2 * lane], bias1 = b_agg0[2 * lane + 1];
        float p0 = 0.f, p1 = 0.f, q0 = 0.f, q1 = 0.f;

        int s0 = half * 16;
        #pragma unroll 2
        for (int si = s0; si < s0 + 16; si += 2) {
            int entA = __shfl_sync(0xffffffffu, ent2, si);
            int entB = __shfl_sync(0xffffffffu, ent2, si + 1);
            int e2A  = entity2edges[entA * NS + lane];
            int e2B  = entity2edges[entB * NS + lane];
            float2 SA = S2[entA * 32 + lane];
            float2 SB = S2[entB * 32 + lane];
            unsigned balA = __ballot_sync(0xffffffffu, e2A == te);
            unsigned balB = __ballot_sync(0xffffffffu, e2B == te);
            float cntA = (float)__popc(balA);
            float cntB = (float)__popc(balB);
            int r1A = __shfl_sync(0xffffffffu, r1, si);
            int r1B = __shfl_sync(0xffffffffu, r1, si + 1);
            float2 eA = R2[r1A * 32 + lane];
            float2 eB = R2[r1B * 32 + lane];
            float mA = __shfl_sync(0xffffffffu, m1, si);
            float mB = __shfl_sync(0xffffffffu, m1, si + 1);
            p0 += mA * fmaxf((SA.x - cntA * corr.x) * (1.f / NS) + eA.x + bias0, 0.f);
            p1 += mA * fmaxf((SA.y - cntA * corr.y) * (1.f / NS) + eA.y + bias1, 0.f);
            q0 += mB * fmaxf((SB.x - cntB * corr.x) * (1.f / NS) + eB.x + bias0, 0.f);
            q1 += mB * fmaxf((SB.y - cntB * corr.y) * (1.f / NS) + eB.y + bias1, 0.f);
        }

        float2 res = make_float2(p0 + q0, p1 + q1);
        if (half == 1) s_sp[tw][lane] = res;
        __syncthreads();
        if (half == 0) {
            float2 o = s_sp[tw][lane];
            s_pre[tw][2 * lane]     = (res.x + o.x) * (1.f / NS);
            s_pre[tw][2 * lane + 1] = (res.y + o.y) * (1.f / NS);
        }
        __syncthreads();
    }

    // ================= staging for MLP / score =============================
    int q = tid >> 6, j = tid & 63;
    if (tid < 256) {
        int i = tid >> 6, jj = tid & 63;
        float ti = t_in[b0 + i];
        if (jj == 0) s_t[i] = ti;
        float q0v = s_pre[i * 2 + 0][jj];
        float q1v = s_pre[i * 2 + 1][jj];
        s_q0[jj * 4 + i] = q0v;
        s_q1[jj * 4 + i] = q1v;
        s_pm[jj * 4 + i] = (1.f - ti) * q0v + ti * q1v;
    }
    __syncthreads();

    // ---- layer 1 partials: pm@A (8 kk per slice), 4 batches per load ----
    {
        float a0 = 0.f, a1 = 0.f, a2 = 0.f, a3 = 0.f;
        int kA = q * 8;
        #pragma unroll
        for (int kk = kA; kk < kA + 8; kk++) {
            float w = g_A[kk * DIM + j];
            a0 += s_pm[kk * 4 + 0] * w;
            a1 += s_pm[kk * 4 + 1] * w;
            a2 += s_pm[kk * 4 + 2] * w;
            a3 += s_pm[kk * 4 + 3] * w;
        }
        s_part[q][0 * 64 + j] = a0;
        s_part[q][1 * 64 + j] = a1;
        s_part[q][2 * 64 + j] = a2;
        s_part[q][3 * 64 + j] = a3;
    }
    __syncthreads();
    if (tid < 256) {
        int i = tid >> 6, jj = tid & 63;
        float s = ((s_part[0][tid] + s_part[1][tid]) + (s_part[2][tid] + s_part[3][tid]))
                + ((s_part[4][tid] + s_part[5][tid]) + (s_part[6][tid] + s_part[7][tid]));
        s += g_E[(b0 + i) * DIM + jj] + g_d[jj] + s_t[i] * mW1[NREL * DIM + jj];
        s_ha[jj * 4 + i] = selu_f(s);
    }
    __syncthreads();

    // ---- layer 2 partials (8 kk each) ----
    {
        float n0 = 0.f, n1 = 0.f, n2 = 0.f, n3 = 0.f;
        int kA = q * 8;
        #pragma unroll
        for (int kk = kA; kk < kA + 8; kk++) {
            float w = mW2[kk * DIM + j];
            n0 += s_ha[kk * 4 + 0] * w;
            n1 += s_ha[kk * 4 + 1] * w;
            n2 += s_ha[kk * 4 + 2] * w;
            n3 += s_ha[kk * 4 + 3] * w;
        }
        s_part[q][0 * 64 + j] = n0;
        s_part[q][1 * 64 + j] = n1;
        s_part[q][2 * 64 + j] = n2;
        s_part[q][3 * 64 + j] = n3;
    }
    __syncthreads();
    if (tid < 256) {
        int i = tid >> 6, jj = tid & 63;
        float s = ((s_part[0][tid] + s_part[1][tid]) + (s_part[2][tid] + s_part[3][tid]))
                + ((s_part[4][tid] + s_part[5][tid]) + (s_part[6][tid] + s_part[7][tid]));
        s_pm[jj * 4 + i] = selu_f(s + mb2[jj]);
    }
    __syncthreads();

    // ---- layer 3 partials ----
    {
        float n0 = 0.f, n1 = 0.f, n2 = 0.f, n3 = 0.f;
        int kA = q * 8;
        #pragma unroll
        for (int kk = kA; kk < kA + 8; kk++) {
            float w = mW3[kk * DIM + j];
            n0 += s_pm[kk * 4 + 0] * w;
            n1 += s_pm[kk * 4 + 1] * w;
            n2 += s_pm[kk * 4 + 2] * w;
            n3 += s_pm[kk * 4 + 3] * w;
        }
        s_part[q][0 * 64 + j] = n0;
        s_part[q][1 * 64 + j] = n1;
        s_part[q][2 * 64 + j] = n2;
        s_part[q][3 * 64 + j] = n3;
    }
    __syncthreads();
    if (tid < 256) {
        int i = tid >> 6, jj = tid & 63;
        float s = ((s_part[0][tid] + s_part[1][tid]) + (s_part[2][tid] + s_part[3][tid]))
                + ((s_part[4][tid] + s_part[5][tid]) + (s_part[6][tid] + s_part[7][tid]));
        s_h3[jj * 4 + i] = selu_f(s + mb3[jj]);
    }
    __syncthreads();

    // ---- score: folded output GEMM + layer 4 + elementwise multiply ----
    {
        int h = tid >> 8, r = tid & 255;
        int jo = r;
        if (jo < NREL) {
            // out partial: h=0 -> q0@Wc0 ; h=1 -> q1@Wc1
            float4 ao = make_float4(0.f, 0.f, 0.f, 0.f);
            const float*  W  = g_Wc + h * DIM * WCS + jo;
            const float4* q4 = (const float4*)(h ? s_q1 : s_q0);
            #pragma unroll 8
            for (int kk = 0; kk < DIM; kk++) {
                float w = W[kk * WCS];
                float4 qv = q4[kk];
                ao.x += qv.x * w; ao.y += qv.y * w;
                ao.z += qv.z * w; ao.w += qv.w * w;
            }
            s_po[tid] = ao;

            // vt partial: h splits kk 0-31 / 32-63 of W4
            float4 av = make_float4(0.f, 0.f, 0.f, 0.f);
            const float*  W4 = g_W4p + jo;
            const float4* h4 = (const float4*)s_h3;
            int k0 = h * 32;
            #pragma unroll 8
            for (int kk = k0; kk < k0 + 32; kk++) {
                float w = W4[kk * WCS];
                float4 hh = h4[kk];
                av.x += hh.x * w; av.y += hh.y * w;
                av.z += hh.z * w; av.w += hh.w * w;
            }
            s_pv[tid] = av;
        }
        __syncthreads();

        if (h == 0 && jo < NREL) {
            float bc = g_bc[jo], m4 = mb4[jo];
            float4 o1 = s_po[tid], o2 = s_po[tid + 256];
            float4 v1 = s_pv[tid], v2 = s_pv[tid + 256];
            out[(b0 + 0) * NREL + jo] = (bc + o1.x + o2.x) * (m4 + v1.x + v2.x);
            out[(b0 + 1) * NREL + jo] = (bc + o1.y + o2.y) * (m4 + v1.y + v2.y);
            out[(b0 + 2) * NREL + jo] = (bc + o1.z + o2.z) * (m4 + v1.z + v2.z);
            out[(b0 + 3) * NREL + jo] = (bc + o1.w + o2.w) * (m4 + v1.w + v2.w);
        }
    }
}

// ---------------- launcher --------------------------------------------------
extern "C" void kernel_launch(void* const* d_in, const int* in_sizes, int n_in,
                              void* d_out, int out_size)
{
    const int*   entity_pairs  = (const int*)d_in[0];
    const int*   train_edges   = (const int*)d_in[1];
    // d_in[2] = labels : dead
    const int*   entity2edges  = (const int*)d_in[3];
    const int*   edge2entities = (const int*)d_in[4];
    const int*   edge2relation = (const int*)d_in[5];
    const float* t             = (const float*)d_in[6];
    const float* eps           = (const float*)d_in[7];
    const float* rel_feat      = (const float*)d_in[8];
    const float* W_agg0        = (const float*)d_in[9];
    const float* b_agg0        = (const float*)d_in[10];
    const float* W_agg1        = (const float*)d_in[11];
    const float* b_agg1        = (const float*)d_in[12];
    const float* W_out         = (const float*)d_in[13];
    const float* b_out         = (const float*)d_in[14];
    const float* mW1           = (const float*)d_in[15];
    const float* mb1           = (const float*)d_in[16];
    const float* mW2           = (const float*)d_in[17];
    const float* mb2           = (const float*)d_in[18];
    const float* mW3           = (const float*)d_in[19];
    const float* mb3           = (const float*)d_in[20];
    const float* mW4           = (const float*)d_in[21];
    const float* mb4           = (const float*)d_in[22];
    float* out = (float*)d_out;

    k_foldR<<<NRELP, 256>>>(rel_feat, W_agg0);
    k_Sw<<<FW_TOTAL + S_BLOCKS, 256>>>(entity2edges, edge2relation,
                                       W_agg1, b_agg1, W_out, b_out,
                                       mW1, mb1, mW4, eps);
    k_fused<<<NB / 4, 512>>>(entity_pairs, train_edges, entity2edges,
                             edge2entities, edge2relation, b_agg0,
                             t, mW1, mW2, mb2, mW3, mb3, mb4, out);
}